// round 10
// baseline (speedup 1.0000x reference)
#include <cuda_runtime.h>
#include <cuda_bf16.h>
#include <math.h>
#include <stdint.h>

// Problem constants
#define N_ROWS 8192
#define DIM 128
#define NTI 64                      // 128-row i-blocks
#define NJOBS 2080                  // pairs of 64-col j-blocks (upper tri)

#define M_MARGIN 0.25f
#define NEG_BIG (-1.0e30f)
#define LN2F 0.6931471805599453f
// gamma' = 256 / ln2 (logits computed in base-2 domain)
#define GP2 369.32993046757465f

// Global bf16 rows (normalized features): [N_ROWS][128]
__device__ __nv_bfloat16 g_h[N_ROWS * DIM];

// Per-job LSE partials + completion counter
__device__ float g_pm[NJOBS];
__device__ float g_ps[NJOBS];
__device__ float g_nm[NJOBS];
__device__ float g_ns[NJOBS];
__device__ unsigned int g_count;

// smem rows: 128 bf16 = 256B data + 16B pad = 272 B/row
#define SROW_B 272
#define TI_BYTES (128 * SROW_B)     // 34816
#define TJ_BYTES (64 * SROW_B)      // 17408

#define SM_TI   0
#define SM_TJ0  TI_BYTES
#define SM_TJ1  (TI_BYTES + TJ_BYTES)
#define SM_LR   (TI_BYTES + 2 * TJ_BYTES)      // 128 ints
#define SM_LC0  (SM_LR + 512)                  // 64 ints
#define SM_LC1  (SM_LC0 + 256)                 // 64 ints
#define SM_RED  (SM_LC1 + 256)                 // 32 floats
#define SM_FLAG (SM_RED + 128)                 // 4 bytes
#define SMEM_TOTAL (SM_FLAG + 16)              // ~71 KB

// ---------------------------------------------------------------------------
__device__ __forceinline__ float ex2(float x) {
    float r;
    asm("ex2.approx.f32 %0, %1;" : "=f"(r) : "f"(x));
    return r;
}
// base-2 logsumexp merge
__device__ __forceinline__ void lse_merge(float& m, float& s, float m2, float s2) {
    float mx = fmaxf(m, m2);
    s = s * ex2(m - mx) + s2 * ex2(m2 - mx);
    m = mx;
}

// ---------------------------------------------------------------------------
// Kernel 1: L2-normalize rows -> bf16 g_h. Warp-per-row, shuffle-only.
// ---------------------------------------------------------------------------
__global__ void __launch_bounds__(256)
prep_kernel(const float* __restrict__ feats) {
    int wid = threadIdx.x >> 5;
    int lane = threadIdx.x & 31;
    int r = blockIdx.x * 8 + wid;

    const float4* src = (const float4*)(feats + (size_t)r * DIM);
    float4 v = src[lane];
    float sq = v.x * v.x + v.y * v.y + v.z * v.z + v.w * v.w;
    #pragma unroll
    for (int o = 16; o > 0; o >>= 1) sq += __shfl_xor_sync(0xffffffffu, sq, o);
    float inv = 1.0f / fmaxf(sqrtf(sq), 1e-12f);

    __nv_bfloat162 p0 = __floats2bfloat162_rn(v.x * inv, v.y * inv);
    __nv_bfloat162 p1 = __floats2bfloat162_rn(v.z * inv, v.w * inv);
    uint2 packed = make_uint2(*(uint32_t*)&p0, *(uint32_t*)&p1);
    ((uint2*)(g_h + (size_t)r * DIM))[lane] = packed;
}

// ---------------------------------------------------------------------------
// mma / ldmatrix / cp.async wrappers
// ---------------------------------------------------------------------------
__device__ __forceinline__ void ldm_x4(uint32_t& r0, uint32_t& r1,
                                       uint32_t& r2, uint32_t& r3,
                                       uint32_t addr) {
    asm volatile("ldmatrix.sync.aligned.m8n8.x4.shared.b16 {%0,%1,%2,%3}, [%4];"
                 : "=r"(r0), "=r"(r1), "=r"(r2), "=r"(r3) : "r"(addr));
}
__device__ __forceinline__ void mma_16816(float* c, const uint32_t* a,
                                          uint32_t b0, uint32_t b1) {
    asm volatile(
        "mma.sync.aligned.m16n8k16.row.col.f32.bf16.bf16.f32 "
        "{%0,%1,%2,%3}, {%4,%5,%6,%7}, {%8,%9}, {%0,%1,%2,%3};"
        : "+f"(c[0]), "+f"(c[1]), "+f"(c[2]), "+f"(c[3])
        : "r"(a[0]), "r"(a[1]), "r"(a[2]), "r"(a[3]), "r"(b0), "r"(b1));
}
__device__ __forceinline__ void cp16(uint32_t dst, const void* src) {
    asm volatile("cp.async.cg.shared.global [%0], [%1], 16;"
                 :: "r"(dst), "l"(src));
}

// pair-jobs per i-block: 64 - ti; offset(ti) = ti*(129-ti)/2
__device__ __forceinline__ int job_offset(int ti) {
    return (ti * (129 - ti)) >> 1;
}

extern __shared__ char smem_dyn[];

// ---------------------------------------------------------------------------
// Mainloop: 128x64 sim, K=128 bf16. acc[2][4][4] per thread (32 regs).
// ---------------------------------------------------------------------------
__device__ __forceinline__ void mainloop(
    uint32_t baseI, uint32_t baseJ, int wid, int lane, float acc[2][4][4])
{
    const int wr = wid >> 1;
    const int wc = wid & 1;

    #pragma unroll
    for (int i = 0; i < 2; ++i)
        #pragma unroll
        for (int j = 0; j < 4; ++j)
            #pragma unroll
            for (int k = 0; k < 4; ++k) acc[i][j][k] = 0.0f;

    const int lrow16 = lane & 15;
    const int lhalf  = lane >> 4;

    uint32_t aAddr[2], bAddr[2];
    #pragma unroll
    for (int mf = 0; mf < 2; ++mf)
        aAddr[mf] = baseI + (uint32_t)((wr * 32 + mf * 16 + lrow16) * SROW_B + lhalf * 16);
    #pragma unroll
    for (int nb = 0; nb < 2; ++nb)
        bAddr[nb] = baseJ + (uint32_t)((wc * 32 + nb * 16 + lrow16) * SROW_B + lhalf * 16);

    #pragma unroll
    for (int ks = 0; ks < DIM / 16; ++ks) {      // 8 k-steps
        uint32_t kByte = (uint32_t)(ks * 32);
        uint32_t a[2][4], bb[2][4];
        #pragma unroll
        for (int mf = 0; mf < 2; ++mf)
            ldm_x4(a[mf][0], a[mf][1], a[mf][2], a[mf][3], aAddr[mf] + kByte);
        #pragma unroll
        for (int nb = 0; nb < 2; ++nb)
            ldm_x4(bb[nb][0], bb[nb][1], bb[nb][2], bb[nb][3], bAddr[nb] + kByte);
        #pragma unroll
        for (int mf = 0; mf < 2; ++mf) {
            #pragma unroll
            for (int nb = 0; nb < 2; ++nb) {
                mma_16816(acc[mf][2 * nb + 0], a[mf], bb[nb][0], bb[nb][2]);
                mma_16816(acc[mf][2 * nb + 1], a[mf], bb[nb][1], bb[nb][3]);
            }
        }
    }
}

// ---------------------------------------------------------------------------
// Epilogue: branch-free two-pass base-2 LSE on acc.
// DIAG: apply gi<gj masking (only needed for diagonal pair-jobs).
// ---------------------------------------------------------------------------
template <bool DIAG>
__device__ __forceinline__ void epilogue(
    float acc[2][4][4], const int* lr, const int* lc,
    int ti, int tjh, int wid, int lane,
    float& MP, float& SP, float& MN, float& SN)
{
    const int wr = wid >> 1;
    const int wc = wid & 1;
    const int grp = lane >> 2;
    const int tid4 = lane & 3;

    int lcv[8];
    #pragma unroll
    for (int nf = 0; nf < 4; ++nf)
        #pragma unroll
        for (int cb = 0; cb < 2; ++cb)
            lcv[nf * 2 + cb] = lc[wc * 32 + nf * 8 + tid4 * 2 + cb];

    float mp = NEG_BIG, mn = NEG_BIG;
    uint32_t eqbits = 0;

    // Pass 1: base-2 logits in-place, per-stream maxes
    #pragma unroll
    for (int mf = 0; mf < 2; ++mf) {
        #pragma unroll
        for (int rh = 0; rh < 2; ++rh) {
            int rloc = wr * 32 + mf * 16 + rh * 8 + grp;
            int li = lr[rloc];
            int gi = ti * 128 + rloc;
            #pragma unroll
            for (int nf = 0; nf < 4; ++nf) {
                #pragma unroll
                for (int cb = 0; cb < 2; ++cb) {
                    float s = acc[mf][nf][rh * 2 + cb];
                    // ln2-domain logits, gamma' folded into FFMA
                    float tn = fmaf(s, GP2, -0.25f * GP2);     // g'(s-0.25)
                    float un = fmaxf(s + M_MARGIN, 0.0f);
                    float ln = tn * un;
                    float tp = fmaf(s, -GP2, 0.75f * GP2);     // g'(0.75-s)
                    float up = fmaxf(1.25f - s, 0.0f);
                    float lp = tp * up;
                    bool eq = (li == lcv[nf * 2 + cb]);
                    float l = eq ? lp : ln;
                    if (DIAG) {
                        int cloc = wc * 32 + nf * 8 + tid4 * 2 + cb;
                        int gj = tjh * 64 + cloc;
                        l = (gi < gj) ? l : -INFINITY;
                        lp = (gi < gj) ? lp : NEG_BIG;
                        ln = (gi < gj) ? ln : NEG_BIG;
                    }
                    acc[mf][nf][rh * 2 + cb] = l;
                    int idx = ((mf * 2 + rh) * 4 + nf) * 2 + cb;
                    eqbits |= (uint32_t)eq << idx;
                    mp = fmaxf(mp, eq ? lp : NEG_BIG);
                    mn = fmaxf(mn, eq ? NEG_BIG : ln);
                }
            }
        }
    }

    // Pass 2: one ex2 per element, predicated accumulate
    float sp = 0.0f, sn = 0.0f;
    #pragma unroll
    for (int mf = 0; mf < 2; ++mf)
        #pragma unroll
        for (int rh = 0; rh < 2; ++rh)
            #pragma unroll
            for (int nf = 0; nf < 4; ++nf)
                #pragma unroll
                for (int cb = 0; cb < 2; ++cb) {
                    int idx = ((mf * 2 + rh) * 4 + nf) * 2 + cb;
                    float l = acc[mf][nf][rh * 2 + cb];
                    bool eq = (eqbits >> idx) & 1u;
                    float e = ex2(l - (eq ? mp : mn));
                    if (eq) sp += e; else sn += e;
                }

    lse_merge(MP, SP, mp, sp);
    lse_merge(MN, SN, mn, sn);
}

// ---------------------------------------------------------------------------
// Kernel 2: pair-job per CTA + fused last-block final reduction.
// ---------------------------------------------------------------------------
__global__ void __launch_bounds__(256, 3)
sim_lse_kernel(const int* __restrict__ labels, float* __restrict__ out) {
    const int bid = blockIdx.x;
    const int t = threadIdx.x;
    const int wid = t >> 5;
    const int lane = t & 31;

    // invert pair-job index: offset(ti) = ti*(129-ti)/2
    int L = bid;
    float disc = 129.0f * 129.0f - 8.0f * (float)L;
    int ti = (int)((129.0f - sqrtf(disc)) * 0.5f);
    if (ti < 0) ti = 0;
    if (ti > NTI - 1) ti = NTI - 1;
    while (ti + 1 <= NTI - 1 && job_offset(ti + 1) <= L) ++ti;
    while (job_offset(ti) > L) --ti;
    const int p = L - job_offset(ti);
    const int tjh0 = 2 * ti + 2 * p;
    const int tjh1 = tjh0 + 1;
    const bool diag = (p == 0);

    char* smem = smem_dyn;
    uint32_t baseI  = (uint32_t)__cvta_generic_to_shared(smem + SM_TI);
    uint32_t baseJ0 = (uint32_t)__cvta_generic_to_shared(smem + SM_TJ0);
    uint32_t baseJ1 = (uint32_t)__cvta_generic_to_shared(smem + SM_TJ1);
    int* lr = (int*)(smem + SM_LR);
    int* lc0 = (int*)(smem + SM_LC0);
    int* lc1 = (int*)(smem + SM_LC1);
    float* red = (float*)(smem + SM_RED);
    unsigned int* flag = (unsigned int*)(smem + SM_FLAG);

    // Load I + J0 + J1 upfront (one async group)
    {
        const char* srcI  = (const char*)(g_h + (size_t)ti * 128 * DIM);
        const char* srcJ0 = (const char*)(g_h + (size_t)tjh0 * 64 * DIM);
        const char* srcJ1 = (const char*)(g_h + (size_t)tjh1 * 64 * DIM);
        #pragma unroll
        for (int it = 0; it < 8; ++it) {
            int idx = t + it * 256;
            int r = idx >> 4, c = idx & 15;
            cp16(baseI + r * SROW_B + c * 16, srcI + idx * 16);
        }
        #pragma unroll
        for (int it = 0; it < 4; ++it) {
            int idx = t + it * 256;
            int r = idx >> 4, c = idx & 15;
            cp16(baseJ0 + r * SROW_B + c * 16, srcJ0 + idx * 16);
        }
        #pragma unroll
        for (int it = 0; it < 4; ++it) {
            int idx = t + it * 256;
            int r = idx >> 4, c = idx & 15;
            cp16(baseJ1 + r * SROW_B + c * 16, srcJ1 + idx * 16);
        }
        asm volatile("cp.async.commit_group;");
    }
    if (t < 128) lr[t] = labels[ti * 128 + t];
    if (t < 64)  lc0[t] = labels[tjh0 * 64 + t];
    if (t >= 64 && t < 128) lc1[t - 64] = labels[tjh1 * 64 + (t - 64)];
    asm volatile("cp.async.wait_group 0;");
    __syncthreads();

    float MP = NEG_BIG, SP = 0.0f, MN = NEG_BIG, SN = 0.0f;
    float acc[2][4][4];

    mainloop(baseI, baseJ0, wid, lane, acc);
    if (diag) epilogue<true >(acc, lr, lc0, ti, tjh0, wid, lane, MP, SP, MN, SN);
    else      epilogue<false>(acc, lr, lc0, ti, tjh0, wid, lane, MP, SP, MN, SN);

    mainloop(baseI, baseJ1, wid, lane, acc);
    if (diag) epilogue<true >(acc, lr, lc1, ti, tjh1, wid, lane, MP, SP, MN, SN);
    else      epilogue<false>(acc, lr, lc1, ti, tjh1, wid, lane, MP, SP, MN, SN);

    // Warp reduction
    #pragma unroll
    for (int o = 16; o > 0; o >>= 1) {
        float m2 = __shfl_xor_sync(0xffffffffu, MP, o);
        float s2 = __shfl_xor_sync(0xffffffffu, SP, o);
        lse_merge(MP, SP, m2, s2);
        m2 = __shfl_xor_sync(0xffffffffu, MN, o);
        s2 = __shfl_xor_sync(0xffffffffu, SN, o);
        lse_merge(MN, SN, m2, s2);
    }

    if (lane == 0) {
        red[wid * 4 + 0] = MP; red[wid * 4 + 1] = SP;
        red[wid * 4 + 2] = MN; red[wid * 4 + 3] = SN;
    }
    __syncthreads();
    if (t == 0) {
        float mp = red[0], sp = red[1], mn = red[2], sn = red[3];
        #pragma unroll
        for (int w = 1; w < 8; ++w) {
            lse_merge(mp, sp, red[w * 4 + 0], red[w * 4 + 1]);
            lse_merge(mn, sn, red[w * 4 + 2], red[w * 4 + 3]);
        }
        g_pm[bid] = mp; g_ps[bid] = sp;
        g_nm[bid] = mn; g_ns[bid] = sn;
        __threadfence();
        unsigned int prev = atomicAdd(&g_count, 1u);
        *flag = (prev == NJOBS - 1) ? 1u : 0u;
    }
    __syncthreads();

    // Last CTA: final reduction + softplus
    if (*flag) {
        __threadfence();
        float mp = NEG_BIG, sp = 0.0f;
        float mn = NEG_BIG, sn = 0.0f;
        for (int i = t; i < NJOBS; i += 256) {
            lse_merge(mp, sp, g_pm[i], g_ps[i]);
            lse_merge(mn, sn, g_nm[i], g_ns[i]);
        }
        #pragma unroll
        for (int o = 16; o > 0; o >>= 1) {
            float m2 = __shfl_xor_sync(0xffffffffu, mp, o);
            float s2 = __shfl_xor_sync(0xffffffffu, sp, o);
            lse_merge(mp, sp, m2, s2);
            m2 = __shfl_xor_sync(0xffffffffu, mn, o);
            s2 = __shfl_xor_sync(0xffffffffu, sn, o);
            lse_merge(mn, sn, m2, s2);
        }
        __syncthreads();   // red smem reuse
        if (lane == 0) {
            red[wid * 4 + 0] = mp; red[wid * 4 + 1] = sp;
            red[wid * 4 + 2] = mn; red[wid * 4 + 3] = sn;
        }
        __syncthreads();
        if (t == 0) {
            float MPf = red[0], SPf = red[1], MNf = red[2], SNf = red[3];
            #pragma unroll
            for (int w = 1; w < 8; ++w) {
                lse_merge(MPf, SPf, red[w * 4 + 0], red[w * 4 + 1]);
                lse_merge(MNf, SNf, red[w * 4 + 2], red[w * 4 + 3]);
            }
            // convert base-2 LSEs back to natural log
            float x = LN2F * (MPf + log2f(SPf) + MNf + log2f(SNf));
            out[0] = fmaxf(x, 0.0f) + log1pf(__expf(-fabsf(x)));
            g_count = 0;   // reset for next graph replay
        }
    }
}

// ---------------------------------------------------------------------------
extern "C" void kernel_launch(void* const* d_in, const int* in_sizes, int n_in,
                              void* d_out, int out_size) {
    const float* feats = (const float*)d_in[0];
    const int* labels = (const int*)d_in[1];
    float* out = (float*)d_out;

    cudaFuncSetAttribute(sim_lse_kernel,
                         cudaFuncAttributeMaxDynamicSharedMemorySize, SMEM_TOTAL);

    prep_kernel<<<N_ROWS / 8, 256>>>(feats);
    sim_lse_kernel<<<NJOBS, 256, SMEM_TOTAL>>>(labels, out);
}

// round 11
// speedup vs baseline: 1.0353x; 1.0353x over previous
#include <cuda_runtime.h>
#include <cuda_bf16.h>
#include <math.h>
#include <stdint.h>

// Problem constants
#define N_ROWS 8192
#define DIM 128
#define NTI 64                      // 128-row i-blocks
#define NJOBS 2080                  // pairs of 64-col j-blocks (upper tri)

#define M_MARGIN 0.25f
#define NEG_BIG (-1.0e30f)
#define LN2F 0.6931471805599453f
// gamma' = 256 / ln2 (logits computed in base-2 domain)
#define GP2 369.32993046757465f

// Global bf16 rows (normalized features): [N_ROWS][128]
__device__ __nv_bfloat16 g_h[N_ROWS * DIM];

// Per-job LSE partials + completion counter
__device__ float g_pm[NJOBS];
__device__ float g_ps[NJOBS];
__device__ float g_nm[NJOBS];
__device__ float g_ns[NJOBS];
__device__ unsigned int g_count;

// smem rows: 128 bf16 = 256B data + 16B pad = 272 B/row
#define SROW_B 272
#define TI_BYTES (128 * SROW_B)     // 34816
#define TJ_BYTES (64 * SROW_B)      // 17408

#define SM_TI   0
#define SM_TJ0  TI_BYTES
#define SM_TJ1  (TI_BYTES + TJ_BYTES)
#define SM_LR   (TI_BYTES + 2 * TJ_BYTES)      // 128 ints
#define SM_LC0  (SM_LR + 512)                  // 64 ints
#define SM_LC1  (SM_LC0 + 256)                 // 64 ints
#define SM_RED  (SM_LC1 + 256)                 // 32 floats
#define SM_FLAG (SM_RED + 128)                 // 4 bytes
#define SMEM_TOTAL (SM_FLAG + 16)              // ~71 KB

// ---------------------------------------------------------------------------
__device__ __forceinline__ float ex2(float x) {
    float r;
    asm("ex2.approx.f32 %0, %1;" : "=f"(r) : "f"(x));
    return r;
}
// base-2 logsumexp merge
__device__ __forceinline__ void lse_merge(float& m, float& s, float m2, float s2) {
    float mx = fmaxf(m, m2);
    s = s * ex2(m - mx) + s2 * ex2(m2 - mx);
    m = mx;
}

// ---------------------------------------------------------------------------
// Kernel 1: L2-normalize rows -> bf16 g_h. Warp-per-row, shuffle-only.
// ---------------------------------------------------------------------------
__global__ void __launch_bounds__(256)
prep_kernel(const float* __restrict__ feats) {
    int wid = threadIdx.x >> 5;
    int lane = threadIdx.x & 31;
    int r = blockIdx.x * 8 + wid;

    const float4* src = (const float4*)(feats + (size_t)r * DIM);
    float4 v = src[lane];
    float sq = v.x * v.x + v.y * v.y + v.z * v.z + v.w * v.w;
    #pragma unroll
    for (int o = 16; o > 0; o >>= 1) sq += __shfl_xor_sync(0xffffffffu, sq, o);
    float inv = 1.0f / fmaxf(sqrtf(sq), 1e-12f);

    __nv_bfloat162 p0 = __floats2bfloat162_rn(v.x * inv, v.y * inv);
    __nv_bfloat162 p1 = __floats2bfloat162_rn(v.z * inv, v.w * inv);
    uint2 packed = make_uint2(*(uint32_t*)&p0, *(uint32_t*)&p1);
    ((uint2*)(g_h + (size_t)r * DIM))[lane] = packed;
}

// ---------------------------------------------------------------------------
// mma / ldmatrix / cp.async wrappers
// ---------------------------------------------------------------------------
__device__ __forceinline__ void ldm_x4(uint32_t& r0, uint32_t& r1,
                                       uint32_t& r2, uint32_t& r3,
                                       uint32_t addr) {
    asm volatile("ldmatrix.sync.aligned.m8n8.x4.shared.b16 {%0,%1,%2,%3}, [%4];"
                 : "=r"(r0), "=r"(r1), "=r"(r2), "=r"(r3) : "r"(addr));
}
__device__ __forceinline__ void mma_16816(float* c, const uint32_t* a,
                                          uint32_t b0, uint32_t b1) {
    asm volatile(
        "mma.sync.aligned.m16n8k16.row.col.f32.bf16.bf16.f32 "
        "{%0,%1,%2,%3}, {%4,%5,%6,%7}, {%8,%9}, {%0,%1,%2,%3};"
        : "+f"(c[0]), "+f"(c[1]), "+f"(c[2]), "+f"(c[3])
        : "r"(a[0]), "r"(a[1]), "r"(a[2]), "r"(a[3]), "r"(b0), "r"(b1));
}
__device__ __forceinline__ void cp16(uint32_t dst, const void* src) {
    asm volatile("cp.async.cg.shared.global [%0], [%1], 16;"
                 :: "r"(dst), "l"(src));
}

// pair-jobs per i-block: 64 - ti; offset(ti) = ti*(129-ti)/2
__device__ __forceinline__ int job_offset(int ti) {
    return (ti * (129 - ti)) >> 1;
}

extern __shared__ char smem_dyn[];

// ---------------------------------------------------------------------------
// Mainloop: 128x64 sim, K=128 bf16. acc[2][4][4] per thread (32 regs).
// ---------------------------------------------------------------------------
__device__ __forceinline__ void mainloop(
    uint32_t baseI, uint32_t baseJ, int wid, int lane, float acc[2][4][4])
{
    const int wr = wid >> 1;
    const int wc = wid & 1;

    #pragma unroll
    for (int i = 0; i < 2; ++i)
        #pragma unroll
        for (int j = 0; j < 4; ++j)
            #pragma unroll
            for (int k = 0; k < 4; ++k) acc[i][j][k] = 0.0f;

    const int lrow16 = lane & 15;
    const int lhalf  = lane >> 4;

    uint32_t aAddr[2], bAddr[2];
    #pragma unroll
    for (int mf = 0; mf < 2; ++mf)
        aAddr[mf] = baseI + (uint32_t)((wr * 32 + mf * 16 + lrow16) * SROW_B + lhalf * 16);
    #pragma unroll
    for (int nb = 0; nb < 2; ++nb)
        bAddr[nb] = baseJ + (uint32_t)((wc * 32 + nb * 16 + lrow16) * SROW_B + lhalf * 16);

    #pragma unroll
    for (int ks = 0; ks < DIM / 16; ++ks) {      // 8 k-steps
        uint32_t kByte = (uint32_t)(ks * 32);
        uint32_t a[2][4], bb[2][4];
        #pragma unroll
        for (int mf = 0; mf < 2; ++mf)
            ldm_x4(a[mf][0], a[mf][1], a[mf][2], a[mf][3], aAddr[mf] + kByte);
        #pragma unroll
        for (int nb = 0; nb < 2; ++nb)
            ldm_x4(bb[nb][0], bb[nb][1], bb[nb][2], bb[nb][3], bAddr[nb] + kByte);
        #pragma unroll
        for (int mf = 0; mf < 2; ++mf) {
            #pragma unroll
            for (int nb = 0; nb < 2; ++nb) {
                mma_16816(acc[mf][2 * nb + 0], a[mf], bb[nb][0], bb[nb][2]);
                mma_16816(acc[mf][2 * nb + 1], a[mf], bb[nb][1], bb[nb][3]);
            }
        }
    }
}

// ---------------------------------------------------------------------------
// Epilogue: branch-free two-pass base-2 LSE on acc. Trimmed op count:
//   tp derived from tn (1 FADD), up derived from un_raw (1 FADD+FMNMX),
//   single masked l (DIAG only), sel-form accumulation (no branches).
// ---------------------------------------------------------------------------
template <bool DIAG>
__device__ __forceinline__ void epilogue(
    float acc[2][4][4], const int* lr, const int* lc,
    int ti, int tjh, int wid, int lane,
    float& MP, float& SP, float& MN, float& SN)
{
    const int wr = wid >> 1;
    const int wc = wid & 1;
    const int grp = lane >> 2;
    const int tid4 = lane & 3;

    int lcv[8];
    #pragma unroll
    for (int nf = 0; nf < 4; ++nf)
        #pragma unroll
        for (int cb = 0; cb < 2; ++cb)
            lcv[nf * 2 + cb] = lc[wc * 32 + nf * 8 + tid4 * 2 + cb];

    float mp = NEG_BIG, mn = NEG_BIG;
    uint32_t eqbits = 0;

    // Pass 1: base-2 logits in-place, per-stream maxes
    #pragma unroll
    for (int mf = 0; mf < 2; ++mf) {
        #pragma unroll
        for (int rh = 0; rh < 2; ++rh) {
            int rloc = wr * 32 + mf * 16 + rh * 8 + grp;
            int li = lr[rloc];
            int gi = ti * 128 + rloc;
            #pragma unroll
            for (int nf = 0; nf < 4; ++nf) {
                #pragma unroll
                for (int cb = 0; cb < 2; ++cb) {
                    float s = acc[mf][nf][rh * 2 + cb];
                    float tn = fmaf(s, GP2, -0.25f * GP2);   // g'(s - 0.25)
                    float un_raw = s + M_MARGIN;
                    float un = fmaxf(un_raw, 0.0f);
                    float ln = tn * un;
                    float tp = 0.5f * GP2 - tn;              // g'(0.75 - s)
                    float up = fmaxf(1.5f - un_raw, 0.0f);   // max(1.25 - s, 0)
                    float lp = tp * up;
                    bool eq = (li == lcv[nf * 2 + cb]);
                    float l = eq ? lp : ln;
                    if (DIAG) {
                        int cloc = wc * 32 + nf * 8 + tid4 * 2 + cb;
                        int gj = tjh * 64 + cloc;
                        l = (gi < gj) ? l : -INFINITY;
                    }
                    acc[mf][nf][rh * 2 + cb] = l;
                    int idx = ((mf * 2 + rh) * 4 + nf) * 2 + cb;
                    eqbits |= (uint32_t)eq << idx;
                    mp = fmaxf(mp, eq ? l : NEG_BIG);
                    mn = fmaxf(mn, eq ? NEG_BIG : l);
                }
            }
        }
    }

    // Pass 2: one ex2 per element, sel-form accumulate (no branches)
    float sp = 0.0f, sn = 0.0f;
    #pragma unroll
    for (int mf = 0; mf < 2; ++mf)
        #pragma unroll
        for (int rh = 0; rh < 2; ++rh)
            #pragma unroll
            for (int nf = 0; nf < 4; ++nf)
                #pragma unroll
                for (int cb = 0; cb < 2; ++cb) {
                    int idx = ((mf * 2 + rh) * 4 + nf) * 2 + cb;
                    float l = acc[mf][nf][rh * 2 + cb];
                    bool eq = (eqbits >> idx) & 1u;
                    float e = ex2(l - (eq ? mp : mn));
                    sp += eq ? e : 0.0f;
                    sn += eq ? 0.0f : e;
                }

    lse_merge(MP, SP, mp, sp);
    lse_merge(MN, SN, mn, sn);
}

// ---------------------------------------------------------------------------
// Kernel 2: pair-job per CTA + fused last-block final reduction.
// ---------------------------------------------------------------------------
__global__ void __launch_bounds__(256, 3)
sim_lse_kernel(const int* __restrict__ labels, float* __restrict__ out) {
    const int bid = blockIdx.x;
    const int t = threadIdx.x;
    const int wid = t >> 5;
    const int lane = t & 31;

    // invert pair-job index: offset(ti) = ti*(129-ti)/2
    int L = bid;
    float disc = 129.0f * 129.0f - 8.0f * (float)L;
    int ti = (int)((129.0f - sqrtf(disc)) * 0.5f);
    if (ti < 0) ti = 0;
    if (ti > NTI - 1) ti = NTI - 1;
    while (ti + 1 <= NTI - 1 && job_offset(ti + 1) <= L) ++ti;
    while (job_offset(ti) > L) --ti;
    const int p = L - job_offset(ti);
    const int tjh0 = 2 * ti + 2 * p;
    const int tjh1 = tjh0 + 1;
    const bool diag = (p == 0);

    char* smem = smem_dyn;
    uint32_t baseI  = (uint32_t)__cvta_generic_to_shared(smem + SM_TI);
    uint32_t baseJ0 = (uint32_t)__cvta_generic_to_shared(smem + SM_TJ0);
    uint32_t baseJ1 = (uint32_t)__cvta_generic_to_shared(smem + SM_TJ1);
    int* lr = (int*)(smem + SM_LR);
    int* lc0 = (int*)(smem + SM_LC0);
    int* lc1 = (int*)(smem + SM_LC1);
    float* red = (float*)(smem + SM_RED);
    unsigned int* flag = (unsigned int*)(smem + SM_FLAG);

    // Load I + J0 + J1 upfront (one async group)
    {
        const char* srcI  = (const char*)(g_h + (size_t)ti * 128 * DIM);
        const char* srcJ0 = (const char*)(g_h + (size_t)tjh0 * 64 * DIM);
        const char* srcJ1 = (const char*)(g_h + (size_t)tjh1 * 64 * DIM);
        #pragma unroll
        for (int it = 0; it < 8; ++it) {
            int idx = t + it * 256;
            int r = idx >> 4, c = idx & 15;
            cp16(baseI + r * SROW_B + c * 16, srcI + idx * 16);
        }
        #pragma unroll
        for (int it = 0; it < 4; ++it) {
            int idx = t + it * 256;
            int r = idx >> 4, c = idx & 15;
            cp16(baseJ0 + r * SROW_B + c * 16, srcJ0 + idx * 16);
        }
        #pragma unroll
        for (int it = 0; it < 4; ++it) {
            int idx = t + it * 256;
            int r = idx >> 4, c = idx & 15;
            cp16(baseJ1 + r * SROW_B + c * 16, srcJ1 + idx * 16);
        }
        asm volatile("cp.async.commit_group;");
    }
    if (t < 128) lr[t] = labels[ti * 128 + t];
    if (t < 64)  lc0[t] = labels[tjh0 * 64 + t];
    if (t >= 64 && t < 128) lc1[t - 64] = labels[tjh1 * 64 + (t - 64)];
    asm volatile("cp.async.wait_group 0;");
    __syncthreads();

    float MP = NEG_BIG, SP = 0.0f, MN = NEG_BIG, SN = 0.0f;
    float acc[2][4][4];

    mainloop(baseI, baseJ0, wid, lane, acc);
    if (diag) epilogue<true >(acc, lr, lc0, ti, tjh0, wid, lane, MP, SP, MN, SN);
    else      epilogue<false>(acc, lr, lc0, ti, tjh0, wid, lane, MP, SP, MN, SN);

    mainloop(baseI, baseJ1, wid, lane, acc);
    if (diag) epilogue<true >(acc, lr, lc1, ti, tjh1, wid, lane, MP, SP, MN, SN);
    else      epilogue<false>(acc, lr, lc1, ti, tjh1, wid, lane, MP, SP, MN, SN);

    // Warp reduction
    #pragma unroll
    for (int o = 16; o > 0; o >>= 1) {
        float m2 = __shfl_xor_sync(0xffffffffu, MP, o);
        float s2 = __shfl_xor_sync(0xffffffffu, SP, o);
        lse_merge(MP, SP, m2, s2);
        m2 = __shfl_xor_sync(0xffffffffu, MN, o);
        s2 = __shfl_xor_sync(0xffffffffu, SN, o);
        lse_merge(MN, SN, m2, s2);
    }

    if (lane == 0) {
        red[wid * 4 + 0] = MP; red[wid * 4 + 1] = SP;
        red[wid * 4 + 2] = MN; red[wid * 4 + 3] = SN;
    }
    __syncthreads();
    if (t == 0) {
        float mp = red[0], sp = red[1], mn = red[2], sn = red[3];
        #pragma unroll
        for (int w = 1; w < 8; ++w) {
            lse_merge(mp, sp, red[w * 4 + 0], red[w * 4 + 1]);
            lse_merge(mn, sn, red[w * 4 + 2], red[w * 4 + 3]);
        }
        g_pm[bid] = mp; g_ps[bid] = sp;
        g_nm[bid] = mn; g_ns[bid] = sn;
        __threadfence();
        unsigned int prev = atomicAdd(&g_count, 1u);
        *flag = (prev == NJOBS - 1) ? 1u : 0u;
    }
    __syncthreads();

    // Last CTA: final reduction + softplus
    if (*flag) {
        __threadfence();
        float mp = NEG_BIG, sp = 0.0f;
        float mn = NEG_BIG, sn = 0.0f;
        for (int i = t; i < NJOBS; i += 256) {
            lse_merge(mp, sp, g_pm[i], g_ps[i]);
            lse_merge(mn, sn, g_nm[i], g_ns[i]);
        }
        #pragma unroll
        for (int o = 16; o > 0; o >>= 1) {
            float m2 = __shfl_xor_sync(0xffffffffu, mp, o);
            float s2 = __shfl_xor_sync(0xffffffffu, sp, o);
            lse_merge(mp, sp, m2, s2);
            m2 = __shfl_xor_sync(0xffffffffu, mn, o);
            s2 = __shfl_xor_sync(0xffffffffu, sn, o);
            lse_merge(mn, sn, m2, s2);
        }
        __syncthreads();   // red smem reuse
        if (lane == 0) {
            red[wid * 4 + 0] = mp; red[wid * 4 + 1] = sp;
            red[wid * 4 + 2] = mn; red[wid * 4 + 3] = sn;
        }
        __syncthreads();
        if (t == 0) {
            float MPf = red[0], SPf = red[1], MNf = red[2], SNf = red[3];
            #pragma unroll
            for (int w = 1; w < 8; ++w) {
                lse_merge(MPf, SPf, red[w * 4 + 0], red[w * 4 + 1]);
                lse_merge(MNf, SNf, red[w * 4 + 2], red[w * 4 + 3]);
            }
            // convert base-2 LSEs back to natural log
            float x = LN2F * (MPf + log2f(SPf) + MNf + log2f(SNf));
            out[0] = fmaxf(x, 0.0f) + log1pf(__expf(-fabsf(x)));
            g_count = 0;   // reset for next graph replay
        }
    }
}

// ---------------------------------------------------------------------------
extern "C" void kernel_launch(void* const* d_in, const int* in_sizes, int n_in,
                              void* d_out, int out_size) {
    const float* feats = (const float*)d_in[0];
    const int* labels = (const int*)d_in[1];
    float* out = (float*)d_out;

    cudaFuncSetAttribute(sim_lse_kernel,
                         cudaFuncAttributeMaxDynamicSharedMemorySize, SMEM_TOTAL);

    prep_kernel<<<N_ROWS / 8, 256>>>(feats);
    sim_lse_kernel<<<NJOBS, 256, SMEM_TOTAL>>>(labels, out);
}

// round 12
// speedup vs baseline: 1.1354x; 1.0966x over previous
#include <cuda_runtime.h>
#include <cuda_bf16.h>
#include <math.h>
#include <stdint.h>

// Problem constants
#define N_ROWS 8192
#define DIM 128
#define NTI 64                      // 128-row i-blocks
#define NJOBS 2080                  // pairs of 64-col j-blocks (upper tri)

#define M_MARGIN 0.25f
#define NEG_BIG (-1.0e30f)
#define LN2F 0.6931471805599453f
// gamma' = 256 / ln2 (logits computed in base-2 domain)
#define GP2 369.32993046757465f

// Global bf16 rows (normalized features): [N_ROWS][128]
__device__ __nv_bfloat16 g_h[N_ROWS * DIM];

// Per-job LSE partials + completion counter
__device__ float g_pm[NJOBS];
__device__ float g_ps[NJOBS];
__device__ float g_nm[NJOBS];
__device__ float g_ns[NJOBS];
__device__ unsigned int g_count;

// smem rows: 128 bf16 = 256B data + 16B pad = 272 B/row
#define SROW_B 272
#define TI_BYTES (128 * SROW_B)     // 34816
#define TJ_BYTES (64 * SROW_B)      // 17408

#define SM_TI   0
#define SM_TJ0  TI_BYTES
#define SM_TJ1  (TI_BYTES + TJ_BYTES)
#define SM_LR   (TI_BYTES + 2 * TJ_BYTES)      // 128 ints
#define SM_LC0  (SM_LR + 512)                  // 64 ints
#define SM_LC1  (SM_LC0 + 256)                 // 64 ints
#define SM_RED  (SM_LC1 + 256)                 // 32 floats
#define SM_FLAG (SM_RED + 128)                 // 4 bytes
#define SMEM_TOTAL (SM_FLAG + 16)              // ~71 KB

// ---------------------------------------------------------------------------
__device__ __forceinline__ float ex2(float x) {
    float r;
    asm("ex2.approx.f32 %0, %1;" : "=f"(r) : "f"(x));
    return r;
}
// base-2 logsumexp merge
__device__ __forceinline__ void lse_merge(float& m, float& s, float m2, float s2) {
    float mx = fmaxf(m, m2);
    s = s * ex2(m - mx) + s2 * ex2(m2 - mx);
    m = mx;
}

// ---------------------------------------------------------------------------
// Kernel 1: L2-normalize rows -> bf16 g_h. Warp-per-row, shuffle-only.
// ---------------------------------------------------------------------------
__global__ void __launch_bounds__(256)
prep_kernel(const float* __restrict__ feats) {
    int wid = threadIdx.x >> 5;
    int lane = threadIdx.x & 31;
    int r = blockIdx.x * 8 + wid;

    const float4* src = (const float4*)(feats + (size_t)r * DIM);
    float4 v = src[lane];
    float sq = v.x * v.x + v.y * v.y + v.z * v.z + v.w * v.w;
    #pragma unroll
    for (int o = 16; o > 0; o >>= 1) sq += __shfl_xor_sync(0xffffffffu, sq, o);
    float inv = 1.0f / fmaxf(sqrtf(sq), 1e-12f);

    __nv_bfloat162 p0 = __floats2bfloat162_rn(v.x * inv, v.y * inv);
    __nv_bfloat162 p1 = __floats2bfloat162_rn(v.z * inv, v.w * inv);
    uint2 packed = make_uint2(*(uint32_t*)&p0, *(uint32_t*)&p1);
    ((uint2*)(g_h + (size_t)r * DIM))[lane] = packed;
}

// ---------------------------------------------------------------------------
// mma / ldmatrix / cp.async wrappers
// ---------------------------------------------------------------------------
__device__ __forceinline__ void ldm_x4(uint32_t& r0, uint32_t& r1,
                                       uint32_t& r2, uint32_t& r3,
                                       uint32_t addr) {
    asm volatile("ldmatrix.sync.aligned.m8n8.x4.shared.b16 {%0,%1,%2,%3}, [%4];"
                 : "=r"(r0), "=r"(r1), "=r"(r2), "=r"(r3) : "r"(addr));
}
__device__ __forceinline__ void mma_16816(float* c, const uint32_t* a,
                                          uint32_t b0, uint32_t b1) {
    asm volatile(
        "mma.sync.aligned.m16n8k16.row.col.f32.bf16.bf16.f32 "
        "{%0,%1,%2,%3}, {%4,%5,%6,%7}, {%8,%9}, {%0,%1,%2,%3};"
        : "+f"(c[0]), "+f"(c[1]), "+f"(c[2]), "+f"(c[3])
        : "r"(a[0]), "r"(a[1]), "r"(a[2]), "r"(a[3]), "r"(b0), "r"(b1));
}
__device__ __forceinline__ void cp16(uint32_t dst, const void* src) {
    asm volatile("cp.async.cg.shared.global [%0], [%1], 16;"
                 :: "r"(dst), "l"(src));
}

// pair-jobs per i-block: 64 - ti; offset(ti) = ti*(129-ti)/2
__device__ __forceinline__ int job_offset(int ti) {
    return (ti * (129 - ti)) >> 1;
}

extern __shared__ char smem_dyn[];

// ---------------------------------------------------------------------------
// Mainloop: 128x64 sim, K=128 bf16. acc[2][4][4] per thread (32 regs).
// ---------------------------------------------------------------------------
__device__ __forceinline__ void mainloop(
    uint32_t baseI, uint32_t baseJ, int wid, int lane, float acc[2][4][4])
{
    const int wr = wid >> 1;
    const int wc = wid & 1;

    #pragma unroll
    for (int i = 0; i < 2; ++i)
        #pragma unroll
        for (int j = 0; j < 4; ++j)
            #pragma unroll
            for (int k = 0; k < 4; ++k) acc[i][j][k] = 0.0f;

    const int lrow16 = lane & 15;
    const int lhalf  = lane >> 4;

    uint32_t aAddr[2], bAddr[2];
    #pragma unroll
    for (int mf = 0; mf < 2; ++mf)
        aAddr[mf] = baseI + (uint32_t)((wr * 32 + mf * 16 + lrow16) * SROW_B + lhalf * 16);
    #pragma unroll
    for (int nb = 0; nb < 2; ++nb)
        bAddr[nb] = baseJ + (uint32_t)((wc * 32 + nb * 16 + lrow16) * SROW_B + lhalf * 16);

    #pragma unroll
    for (int ks = 0; ks < DIM / 16; ++ks) {      // 8 k-steps
        uint32_t kByte = (uint32_t)(ks * 32);
        uint32_t a[2][4], bb[2][4];
        #pragma unroll
        for (int mf = 0; mf < 2; ++mf)
            ldm_x4(a[mf][0], a[mf][1], a[mf][2], a[mf][3], aAddr[mf] + kByte);
        #pragma unroll
        for (int nb = 0; nb < 2; ++nb)
            ldm_x4(bb[nb][0], bb[nb][1], bb[nb][2], bb[nb][3], bAddr[nb] + kByte);
        #pragma unroll
        for (int mf = 0; mf < 2; ++mf) {
            #pragma unroll
            for (int nb = 0; nb < 2; ++nb) {
                mma_16816(acc[mf][2 * nb + 0], a[mf], bb[nb][0], bb[nb][2]);
                mma_16816(acc[mf][2 * nb + 1], a[mf], bb[nb][1], bb[nb][3]);
            }
        }
    }
}

// ---------------------------------------------------------------------------
// Epilogue: sparse-positive two-pass base-2 LSE.
// Common path (neg, ~99%): no selects. Rare eq elements diverted into the
// positive stream via a divergent branch and excluded from neg with -inf.
// ---------------------------------------------------------------------------
template <bool DIAG>
__device__ __forceinline__ void epilogue(
    float acc[2][4][4], const int* lr, const int* lc,
    int ti, int tjh, int wid, int lane,
    float& MP, float& SP, float& MN, float& SN)
{
    const int wr = wid >> 1;
    const int wc = wid & 1;
    const int grp = lane >> 2;
    const int tid4 = lane & 3;

    int lcv[8];
    #pragma unroll
    for (int nf = 0; nf < 4; ++nf)
        #pragma unroll
        for (int cb = 0; cb < 2; ++cb)
            lcv[nf * 2 + cb] = lc[wc * 32 + nf * 8 + tid4 * 2 + cb];

    float mp = NEG_BIG, sp = 0.0f, mn = NEG_BIG;

    // Pass 1: neg logits in-place; eq elements -> pos stream (rare branch)
    #pragma unroll
    for (int mf = 0; mf < 2; ++mf) {
        #pragma unroll
        for (int rh = 0; rh < 2; ++rh) {
            int rloc = wr * 32 + mf * 16 + rh * 8 + grp;
            int li = lr[rloc];
            int gi = ti * 128 + rloc;
            #pragma unroll
            for (int nf = 0; nf < 4; ++nf) {
                #pragma unroll
                for (int cb = 0; cb < 2; ++cb) {
                    float s = acc[mf][nf][rh * 2 + cb];
                    float tn = fmaf(s, GP2, -0.25f * GP2);   // g'(s - 0.25)
                    float un_raw = s + M_MARGIN;
                    float ln = tn * fmaxf(un_raw, 0.0f);
                    bool eq = (li == lcv[nf * 2 + cb]);
                    if (DIAG) {
                        int cloc = wc * 32 + nf * 8 + tid4 * 2 + cb;
                        bool valid = gi < tjh * 64 + cloc;
                        eq = eq && valid;
                        ln = valid ? ln : -INFINITY;
                    }
                    if (eq) {                                // ~1% of elements
                        float tp = 0.5f * GP2 - tn;          // g'(0.75 - s)
                        float lp = tp * fmaxf(1.5f - un_raw, 0.0f);
                        float mx = fmaxf(mp, lp);
                        sp = sp * ex2(mp - mx) + ex2(lp - mx);
                        mp = mx;
                        ln = -INFINITY;                      // exclude from neg
                    }
                    acc[mf][nf][rh * 2 + cb] = ln;
                    mn = fmaxf(mn, ln);
                }
            }
        }
    }

    // Pass 2: unconditional neg accumulate (excluded elements give ex2 -> 0)
    float sn = 0.0f;
    #pragma unroll
    for (int mf = 0; mf < 2; ++mf)
        #pragma unroll
        for (int rh = 0; rh < 2; ++rh)
            #pragma unroll
            for (int nf = 0; nf < 4; ++nf)
                #pragma unroll
                for (int cb = 0; cb < 2; ++cb)
                    sn += ex2(acc[mf][nf][rh * 2 + cb] - mn);

    lse_merge(MP, SP, mp, sp);
    lse_merge(MN, SN, mn, sn);
}

// ---------------------------------------------------------------------------
// Kernel 2: pair-job per CTA + fused last-block final reduction.
// ---------------------------------------------------------------------------
__global__ void __launch_bounds__(256, 3)
sim_lse_kernel(const int* __restrict__ labels, float* __restrict__ out) {
    const int bid = blockIdx.x;
    const int t = threadIdx.x;
    const int wid = t >> 5;
    const int lane = t & 31;

    // invert pair-job index: offset(ti) = ti*(129-ti)/2
    int L = bid;
    float disc = 129.0f * 129.0f - 8.0f * (float)L;
    int ti = (int)((129.0f - sqrtf(disc)) * 0.5f);
    if (ti < 0) ti = 0;
    if (ti > NTI - 1) ti = NTI - 1;
    while (ti + 1 <= NTI - 1 && job_offset(ti + 1) <= L) ++ti;
    while (job_offset(ti) > L) --ti;
    const int p = L - job_offset(ti);
    const int tjh0 = 2 * ti + 2 * p;
    const int tjh1 = tjh0 + 1;
    const bool diag = (p == 0);

    char* smem = smem_dyn;
    uint32_t baseI  = (uint32_t)__cvta_generic_to_shared(smem + SM_TI);
    uint32_t baseJ0 = (uint32_t)__cvta_generic_to_shared(smem + SM_TJ0);
    uint32_t baseJ1 = (uint32_t)__cvta_generic_to_shared(smem + SM_TJ1);
    int* lr = (int*)(smem + SM_LR);
    int* lc0 = (int*)(smem + SM_LC0);
    int* lc1 = (int*)(smem + SM_LC1);
    float* red = (float*)(smem + SM_RED);
    unsigned int* flag = (unsigned int*)(smem + SM_FLAG);

    // Load I + J0 + J1 upfront (one async group)
    {
        const char* srcI  = (const char*)(g_h + (size_t)ti * 128 * DIM);
        const char* srcJ0 = (const char*)(g_h + (size_t)tjh0 * 64 * DIM);
        const char* srcJ1 = (const char*)(g_h + (size_t)tjh1 * 64 * DIM);
        #pragma unroll
        for (int it = 0; it < 8; ++it) {
            int idx = t + it * 256;
            int r = idx >> 4, c = idx & 15;
            cp16(baseI + r * SROW_B + c * 16, srcI + idx * 16);
        }
        #pragma unroll
        for (int it = 0; it < 4; ++it) {
            int idx = t + it * 256;
            int r = idx >> 4, c = idx & 15;
            cp16(baseJ0 + r * SROW_B + c * 16, srcJ0 + idx * 16);
        }
        #pragma unroll
        for (int it = 0; it < 4; ++it) {
            int idx = t + it * 256;
            int r = idx >> 4, c = idx & 15;
            cp16(baseJ1 + r * SROW_B + c * 16, srcJ1 + idx * 16);
        }
        asm volatile("cp.async.commit_group;");
    }
    if (t < 128) lr[t] = labels[ti * 128 + t];
    if (t < 64)  lc0[t] = labels[tjh0 * 64 + t];
    if (t >= 64 && t < 128) lc1[t - 64] = labels[tjh1 * 64 + (t - 64)];
    asm volatile("cp.async.wait_group 0;");
    __syncthreads();

    float MP = NEG_BIG, SP = 0.0f, MN = NEG_BIG, SN = 0.0f;
    float acc[2][4][4];

    mainloop(baseI, baseJ0, wid, lane, acc);
    if (diag) epilogue<true >(acc, lr, lc0, ti, tjh0, wid, lane, MP, SP, MN, SN);
    else      epilogue<false>(acc, lr, lc0, ti, tjh0, wid, lane, MP, SP, MN, SN);

    mainloop(baseI, baseJ1, wid, lane, acc);
    if (diag) epilogue<true >(acc, lr, lc1, ti, tjh1, wid, lane, MP, SP, MN, SN);
    else      epilogue<false>(acc, lr, lc1, ti, tjh1, wid, lane, MP, SP, MN, SN);

    // Warp reduction
    #pragma unroll
    for (int o = 16; o > 0; o >>= 1) {
        float m2 = __shfl_xor_sync(0xffffffffu, MP, o);
        float s2 = __shfl_xor_sync(0xffffffffu, SP, o);
        lse_merge(MP, SP, m2, s2);
        m2 = __shfl_xor_sync(0xffffffffu, MN, o);
        s2 = __shfl_xor_sync(0xffffffffu, SN, o);
        lse_merge(MN, SN, m2, s2);
    }

    if (lane == 0) {
        red[wid * 4 + 0] = MP; red[wid * 4 + 1] = SP;
        red[wid * 4 + 2] = MN; red[wid * 4 + 3] = SN;
    }
    __syncthreads();
    if (t == 0) {
        float mp = red[0], sp = red[1], mn = red[2], sn = red[3];
        #pragma unroll
        for (int w = 1; w < 8; ++w) {
            lse_merge(mp, sp, red[w * 4 + 0], red[w * 4 + 1]);
            lse_merge(mn, sn, red[w * 4 + 2], red[w * 4 + 3]);
        }
        g_pm[bid] = mp; g_ps[bid] = sp;
        g_nm[bid] = mn; g_ns[bid] = sn;
        __threadfence();
        unsigned int prev = atomicAdd(&g_count, 1u);
        *flag = (prev == NJOBS - 1) ? 1u : 0u;
    }
    __syncthreads();

    // Last CTA: final reduction + softplus
    if (*flag) {
        __threadfence();
        float mp = NEG_BIG, sp = 0.0f;
        float mn = NEG_BIG, sn = 0.0f;
        for (int i = t; i < NJOBS; i += 256) {
            lse_merge(mp, sp, g_pm[i], g_ps[i]);
            lse_merge(mn, sn, g_nm[i], g_ns[i]);
        }
        #pragma unroll
        for (int o = 16; o > 0; o >>= 1) {
            float m2 = __shfl_xor_sync(0xffffffffu, mp, o);
            float s2 = __shfl_xor_sync(0xffffffffu, sp, o);
            lse_merge(mp, sp, m2, s2);
            m2 = __shfl_xor_sync(0xffffffffu, mn, o);
            s2 = __shfl_xor_sync(0xffffffffu, sn, o);
            lse_merge(mn, sn, m2, s2);
        }
        __syncthreads();   // red smem reuse
        if (lane == 0) {
            red[wid * 4 + 0] = mp; red[wid * 4 + 1] = sp;
            red[wid * 4 + 2] = mn; red[wid * 4 + 3] = sn;
        }
        __syncthreads();
        if (t == 0) {
            float MPf = red[0], SPf = red[1], MNf = red[2], SNf = red[3];
            #pragma unroll
            for (int w = 1; w < 8; ++w) {
                lse_merge(MPf, SPf, red[w * 4 + 0], red[w * 4 + 1]);
                lse_merge(MNf, SNf, red[w * 4 + 2], red[w * 4 + 3]);
            }
            // convert base-2 LSEs back to natural log
            float x = LN2F * (MPf + log2f(SPf) + MNf + log2f(SNf));
            out[0] = fmaxf(x, 0.0f) + log1pf(__expf(-fabsf(x)));
            g_count = 0;   // reset for next graph replay
        }
    }
}

// ---------------------------------------------------------------------------
extern "C" void kernel_launch(void* const* d_in, const int* in_sizes, int n_in,
                              void* d_out, int out_size) {
    const float* feats = (const float*)d_in[0];
    const int* labels = (const int*)d_in[1];
    float* out = (float*)d_out;

    cudaFuncSetAttribute(sim_lse_kernel,
                         cudaFuncAttributeMaxDynamicSharedMemorySize, SMEM_TOTAL);

    prep_kernel<<<N_ROWS / 8, 256>>>(feats);
    sim_lse_kernel<<<NJOBS, 256, SMEM_TOTAL>>>(labels, out);
}